// round 10
// baseline (speedup 1.0000x reference)
#include <cuda_runtime.h>
#include <math.h>

#define BB 512
#define NN 64
#define EE 512
#define AA 16
#define ITERS 8

#define THREADS 512
#define EHALF (EE / 2)          // edges per CTA (cluster of 2 CTAs per batch)

// ---------------- global message buffers (L2-resident, 16MB each) -----------
__device__ float g_mf[BB * EE * AA];
__device__ float g_mb[BB * EE * AA];

#define CLUSTER_ARRIVE() asm volatile("barrier.cluster.arrive.aligned;" ::: "memory")
#define CLUSTER_WAIT()   asm volatile("barrier.cluster.wait.aligned;"   ::: "memory")

// ---------------- fused kernel: 2-CTA cluster per batch ---------------------
// Each CTA owns 256 edges (message phase); q/argmax/eval are computed
// redundantly and bit-identically in both CTAs. Messages live in global
// memory so both CTAs see all of them after the cluster barrier.
__global__ void __launch_bounds__(THREADS, 2) __cluster_dims__(2, 1, 1)
k_main(const float* __restrict__ node_vals,
       const float* __restrict__ edge_vals,
       const int* __restrict__ ef_g,
       const int* __restrict__ et_g,
       float* __restrict__ out, int out_size)
{
    __shared__ float s_q [NN * AA];         // 4 KB
    __shared__ float s_nv[NN * AA];         // 4 KB
    __shared__ int   s_ef[EE];
    __shared__ int   s_et[EE];
    __shared__ int   s_ino[NN + 1];
    __shared__ int   s_out[NN + 1];
    __shared__ int   s_inl[EE];
    __shared__ int   s_onl[EE];
    __shared__ int   s_a [NN];
    __shared__ int   s_am[NN];
    __shared__ float s_red[16];
    __shared__ float sh_qmax;
    __shared__ int   sh_flag;

    const int b    = blockIdx.x >> 1;       // batch
    const int half = blockIdx.x & 1;        // cluster rank: edge half owner
    const int tid  = threadIdx.x;           // 512
    const int lane = tid & 31;
    const int warp = tid >> 5;              // 0..15
    const unsigned full = 0xffffffffu;

    // ---------------- init: node state + zero OWN message half ----------------
    {
        const float* nvp = node_vals + (size_t)b * NN * AA;
        #pragma unroll
        for (int p = 0; p < 2; p++) {
            int i = tid + p * THREADS;      // 0..1023
            float v = nvp[i];
            s_nv[i] = v;
            s_q[i]  = v * (1.0f / NN);
        }
        // zero own half of messages: EHALF*AA = 4096 floats = 1024 float4 per dir
        float4 z = make_float4(0.f, 0.f, 0.f, 0.f);
        float4* mf4 = (float4*)(g_mf + ((size_t)b * EE + half * EHALF) * AA);
        float4* mb4 = (float4*)(g_mb + ((size_t)b * EE + half * EHALF) * AA);
        #pragma unroll
        for (int p = 0; p < 2; p++) {
            mf4[tid + p * THREADS] = z;
            mb4[tid + p * THREADS] = z;
        }
        s_ef[tid] = ef_g[tid];
        s_et[tid] = et_g[tid];
        if (tid == 0) { sh_qmax = -INFINITY; sh_flag = 0; }
    }
    __syncthreads();

    // ---------------- initial per-node argmax over RAW node_vals -------------
    {
        #pragma unroll
        for (int p = 0; p < 2; p++) {
            int n = (tid >> 4) + p * 32;
            int a = tid & 15;
            float bv = s_nv[n * AA + a]; int bi = a;
            #pragma unroll
            for (int m = 1; m < 16; m <<= 1) {
                float ov = __shfl_xor_sync(full, bv, m, 16);
                int   oi = __shfl_xor_sync(full, bi, m, 16);
                if (ov > bv || (ov == bv && oi < bi)) { bv = ov; bi = oi; }
            }
            if (a == 0) s_a[n] = bi;
        }
    }

    // ---------------- CSR adjacency build (deterministic, ascending e) ------
    {
        if (tid < NN) {
            int c = 0;
            for (int e = 0; e < EE; e++) if (s_et[e] == tid) c++;
            s_ino[tid + 1] = c;
        } else if (tid < 2 * NN) {
            int n = tid - NN; int c = 0;
            for (int e = 0; e < EE; e++) if (s_ef[e] == n) c++;
            s_out[n + 1] = c;
        }
        __syncthreads();
        if (tid == 0) {
            s_ino[0] = 0; s_out[0] = 0;
            for (int n = 0; n < NN; n++) {
                s_ino[n + 1] += s_ino[n];
                s_out[n + 1] += s_out[n];
            }
        }
        __syncthreads();
        if (tid < NN) {
            int c = s_ino[tid];
            for (int e = 0; e < EE; e++) if (s_et[e] == tid) s_inl[c++] = e;
        } else if (tid < 2 * NN) {
            int n = tid - NN; int c = s_out[n];
            for (int e = 0; e < EE; e++) if (s_ef[e] == n) s_onl[c++] = e;
        }
    }
    __syncthreads();

    // ---------------- eval helper (identical in both CTAs) ----------------
    auto do_eval = [&]() {
        float contrib = 0.f;
        if (tid < NN)
            contrib += s_nv[tid * AA + s_a[tid]] * (1.0f / NN);
        {
            int e  = tid;                        // 512 threads == EE
            int af = s_a[s_ef[e]];
            int at = s_a[s_et[e]];
            contrib += __ldg(&edge_vals[(((size_t)b * EE + e) * AA + af) * AA + at])
                       * (1.0f / EE);
        }
        #pragma unroll
        for (int m = 16; m > 0; m >>= 1)
            contrib += __shfl_xor_sync(full, contrib, m);
        if (lane == 0) s_red[warp] = contrib;
        __syncthreads();
        if (warp == 0) {
            float v = (lane < 16) ? s_red[lane] : 0.f;
            #pragma unroll
            for (int m = 8; m > 0; m >>= 1)
                v += __shfl_xor_sync(full, v, m, 16);
            if (lane == 0) {
                if (v > sh_qmax) { sh_qmax = v; sh_flag = 1; }
                else             { sh_flag = 0; }
            }
        }
        __syncthreads();
        if (sh_flag && tid < NN) s_am[tid] = s_a[tid];
        __syncthreads();
    };

    do_eval();   // iteration-0 eval of raw argmax assignment

    // cluster barrier: message zeroing + init visible before loop
    CLUSTER_ARRIVE(); CLUSTER_WAIT();

    const int tsel = lane >> 4;      // which of the warp's 2 concurrent tiles
    const int tl   = lane & 15;      // lane within tile
    const int rg   = tl >> 2;        // row group: rows 4*rg .. 4*rg+3
    const int kg   = tl & 3;         // col group: cols 4*kg .. 4*kg+3

    // ---------------- 8 message-passing iterations ----------------
    for (int it = 0; it < ITERS; it++) {
        // ---- message phase: this CTA's 256 edges; 16 lanes/tile, 4x4 blocks ----
        {
            const float sc = 1.0f / EE;
            #pragma unroll 2
            for (int i = 0; i < 8; i++) {
                int e = half * EHALF + (warp << 4) + (i << 1) + tsel;
                const float4* tile4 =
                    (const float4*)(edge_vals + (((size_t)b * EE + e) << 8));
                int nf = s_ef[e], nt = s_et[e];
                float* mfp = g_mf + (((size_t)b * EE + e) << 4);
                float* mbp = g_mb + (((size_t)b * EE + e) << 4);

                // d[at] = q[to][at] - mf_old[at]   (this lane's 4 cols, group kg)
                float4 qt4  = ((const float4*)(s_q + (nt << 4)))[kg];
                float4 mfo4 = ((const float4*)mfp)[kg];
                float4 d4 = make_float4(qt4.x - mfo4.x, qt4.y - mfo4.y,
                                        qt4.z - mfo4.z, qt4.w - mfo4.w);
                // c[af] = q[from][af] - mb_old[af] (this lane's 4 rows, group rg)
                float4 qf4  = ((const float4*)(s_q + (nf << 4)))[rg];
                float4 mbo4 = ((const float4*)mbp)[rg];
                float4 c4 = make_float4(qf4.x - mbo4.x, qf4.y - mbo4.y,
                                        qf4.z - mbo4.z, qf4.w - mbo4.w);

                float4 f4, m4, v;
                int base = (rg << 4) + kg;      // float4 index of (row 4rg, colgrp kg)

                // j = 0 : row 4rg+0
                v = __ldg(tile4 + base);
                v.x *= sc; v.y *= sc; v.z *= sc; v.w *= sc;
                m4.x = fmaxf(fmaxf(d4.x + v.x, d4.y + v.y),
                             fmaxf(d4.z + v.z, d4.w + v.w));
                f4.x = c4.x + v.x; f4.y = c4.x + v.y;
                f4.z = c4.x + v.z; f4.w = c4.x + v.w;
                // j = 1 : row 4rg+1
                v = __ldg(tile4 + base + 4);
                v.x *= sc; v.y *= sc; v.z *= sc; v.w *= sc;
                m4.y = fmaxf(fmaxf(d4.x + v.x, d4.y + v.y),
                             fmaxf(d4.z + v.z, d4.w + v.w));
                f4.x = fmaxf(f4.x, c4.y + v.x); f4.y = fmaxf(f4.y, c4.y + v.y);
                f4.z = fmaxf(f4.z, c4.y + v.z); f4.w = fmaxf(f4.w, c4.y + v.w);
                // j = 2 : row 4rg+2
                v = __ldg(tile4 + base + 8);
                v.x *= sc; v.y *= sc; v.z *= sc; v.w *= sc;
                m4.z = fmaxf(fmaxf(d4.x + v.x, d4.y + v.y),
                             fmaxf(d4.z + v.z, d4.w + v.w));
                f4.x = fmaxf(f4.x, c4.z + v.x); f4.y = fmaxf(f4.y, c4.z + v.y);
                f4.z = fmaxf(f4.z, c4.z + v.z); f4.w = fmaxf(f4.w, c4.z + v.w);
                // j = 3 : row 4rg+3
                v = __ldg(tile4 + base + 12);
                v.x *= sc; v.y *= sc; v.z *= sc; v.w *= sc;
                m4.w = fmaxf(fmaxf(d4.x + v.x, d4.y + v.y),
                             fmaxf(d4.z + v.z, d4.w + v.w));
                f4.x = fmaxf(f4.x, c4.w + v.x); f4.y = fmaxf(f4.y, c4.w + v.y);
                f4.z = fmaxf(f4.z, c4.w + v.z); f4.w = fmaxf(f4.w, c4.w + v.w);

                // reduce row-maxes (mb) over the 4 col-groups: xor 1, 2 (exact max)
                m4.x = fmaxf(m4.x, __shfl_xor_sync(full, m4.x, 1));
                m4.y = fmaxf(m4.y, __shfl_xor_sync(full, m4.y, 1));
                m4.z = fmaxf(m4.z, __shfl_xor_sync(full, m4.z, 1));
                m4.w = fmaxf(m4.w, __shfl_xor_sync(full, m4.w, 1));
                m4.x = fmaxf(m4.x, __shfl_xor_sync(full, m4.x, 2));
                m4.y = fmaxf(m4.y, __shfl_xor_sync(full, m4.y, 2));
                m4.z = fmaxf(m4.z, __shfl_xor_sync(full, m4.z, 2));
                m4.w = fmaxf(m4.w, __shfl_xor_sync(full, m4.w, 2));

                // reduce col-maxes (mf) over the 4 row-groups: xor 4, 8 (exact max)
                f4.x = fmaxf(f4.x, __shfl_xor_sync(full, f4.x, 4));
                f4.y = fmaxf(f4.y, __shfl_xor_sync(full, f4.y, 4));
                f4.z = fmaxf(f4.z, __shfl_xor_sync(full, f4.z, 4));
                f4.w = fmaxf(f4.w, __shfl_xor_sync(full, f4.w, 4));
                f4.x = fmaxf(f4.x, __shfl_xor_sync(full, f4.x, 8));
                f4.y = fmaxf(f4.y, __shfl_xor_sync(full, f4.y, 8));
                f4.z = fmaxf(f4.z, __shfl_xor_sync(full, f4.z, 8));
                f4.w = fmaxf(f4.w, __shfl_xor_sync(full, f4.w, 8));

                // mean-center mf over 16 'at' (serial 4 + xor1 + xor2)
                float s = f4.x + f4.y + f4.z + f4.w;
                s += __shfl_xor_sync(full, s, 1);
                s += __shfl_xor_sync(full, s, 2);
                s *= (1.0f / AA);
                f4.x -= s; f4.y -= s; f4.z -= s; f4.w -= s;

                // mean-center mb over 16 'af' — exact R6 sum tree
                float4 t4;
                t4.x = m4.x + __shfl_xor_sync(full, m4.x, 8);
                t4.y = m4.y + __shfl_xor_sync(full, m4.y, 8);
                t4.z = m4.z + __shfl_xor_sync(full, m4.z, 8);
                t4.w = m4.w + __shfl_xor_sync(full, m4.w, 8);
                float sm = (t4.x + t4.y) + (t4.z + t4.w);
                sm += __shfl_xor_sync(full, sm, 4);
                sm *= (1.0f / AA);
                m4.x -= sm; m4.y -= sm; m4.z -= sm; m4.w -= sm;

                if (rg == 0) ((float4*)mfp)[kg] = f4;
                if (kg == 0) ((float4*)mbp)[rg] = m4;
            }
        }

        // cluster barrier #1: both halves' messages visible (release/acquire)
        CLUSTER_ARRIVE(); CLUSTER_WAIT();

        // ---- node update + argmax (full, redundant in both CTAs) ----
        {
            const float* mfb = g_mf + (((size_t)b * EE) << 4);
            const float* mbb = g_mb + (((size_t)b * EE) << 4);
            #pragma unroll
            for (int p = 0; p < 2; p++) {
                int n = (tid >> 4) + p * 32;
                int a = tid & 15;
                float v = s_nv[n * AA + a] * (1.0f / NN);
                int i0 = s_ino[n], i1 = s_ino[n + 1];
                for (int i = i0; i < i1; i++) v += mfb[(s_inl[i] << 4) + a];
                int o0 = s_out[n], o1 = s_out[n + 1];
                for (int i = o0; i < o1; i++) v += mbb[(s_onl[i] << 4) + a];
                s_q[n * AA + a] = v;

                float bv = v; int bi = a;
                #pragma unroll
                for (int m = 1; m < 16; m <<= 1) {
                    float ov = __shfl_xor_sync(full, bv, m, 16);
                    int   oi = __shfl_xor_sync(full, bi, m, 16);
                    if (ov > bv || (ov == bv && oi < bi)) { bv = ov; bi = oi; }
                }
                if (a == 0) s_a[n] = bi;
            }
        }
        __syncthreads();

        // ---- eval current assignment, keep best ----
        do_eval();

        // cluster barrier #2: peer done reading old messages before we overwrite
        CLUSTER_ARRIVE(); CLUSTER_WAIT();
    }

    // ---------------- write results (rank 0 only) ----------------
    if (half == 0) {
        int tot = BB + BB * NN;
        if (out_size >= tot) {
            if (tid == 0) out[b] = sh_qmax;
            if (tid < NN) out[BB + b * NN + tid] = (float)s_am[tid];
        } else if (out_size == BB * NN) {
            if (tid < NN) out[b * NN + tid] = (float)s_am[tid];
        } else {
            if (tid == 0 && b < out_size) out[b] = sh_qmax;
        }
    }
}

// ---------------- launch ----------------------------------------------------
extern "C" void kernel_launch(void* const* d_in, const int* in_sizes, int n_in,
                              void* d_out, int out_size) {
    const float* node_vals = (const float*)d_in[0];
    const float* edge_vals = (const float*)d_in[1];
    const int*   ef        = (const int*)d_in[2];
    const int*   et        = (const int*)d_in[3];
    float* out = (float*)d_out;

    k_main<<<BB * 2, THREADS>>>(node_vals, edge_vals, ef, et, out, out_size);
}

// round 11
// speedup vs baseline: 1.2996x; 1.2996x over previous
#include <cuda_runtime.h>
#include <math.h>

#define BB 512
#define NN 64
#define EE 512
#define AA 16
#define ITERS 8

#define THREADS 1024
// SMEM: mf 32K + mb 32K + q 4K + nv 4K + ef/et 4K + csr ~4.7K + misc ~1K
#define SMEM_BYTES (82 * 1024)

// ---------------- fused persistent kernel: one CTA per batch ----------------
// 1024 threads x 64 regs = full RF -> exactly 1 CTA/SM. Resident edge
// working set = 148 x 512KB = 74MB < L2 (126MB): edges stream from HBM once,
// then serve from L2 for iterations 2..8. All state lives in SMEM.
__global__ void __launch_bounds__(THREADS, 1) k_main(
    const float* __restrict__ node_vals,
    const float* __restrict__ edge_vals,
    const int* __restrict__ ef_g,
    const int* __restrict__ et_g,
    float* __restrict__ out, int out_size)
{
    extern __shared__ float smem[];
    float* s_mf  = smem;                    // 8192 floats (32 KB)
    float* s_mb  = s_mf + EE * AA;          // 8192 floats (32 KB)
    float* s_q   = s_mb + EE * AA;          // 1024 floats (4 KB)
    float* s_nv  = s_q  + NN * AA;          // 1024 floats (4 KB)
    int*   s_ef  = (int*)(s_nv + NN * AA);  // 512
    int*   s_et  = s_ef + EE;               // 512
    int*   s_ino = s_et + EE;               // 65
    int*   s_out = s_ino + NN + 1;          // 65
    int*   s_inl = s_out + NN + 1;          // 512
    int*   s_onl = s_inl + EE;              // 512
    int*   s_a   = s_onl + EE;              // 64
    int*   s_am  = s_a  + NN;               // 64
    float* s_red = (float*)(s_am + NN);     // 32

    __shared__ float sh_qmax;
    __shared__ int   sh_flag;

    const int b    = blockIdx.x;
    const int tid  = threadIdx.x;           // 1024
    const int lane = tid & 31;
    const int warp = tid >> 5;              // 0..31
    const unsigned full = 0xffffffffu;

    // ---------------- init: load inputs, zero messages ----------------
    {
        const float* nvp = node_vals + (size_t)b * NN * AA;
        float v = nvp[tid];                 // 1024 == NN*AA
        s_nv[tid] = v;
        s_q[tid]  = v * (1.0f / NN);
        float4 z = make_float4(0.f, 0.f, 0.f, 0.f);
        #pragma unroll
        for (int p = 0; p < 4; p++)
            ((float4*)s_mf)[tid + p * THREADS] = z;   // covers s_mf then s_mb
        if (tid < EE)            s_ef[tid] = ef_g[tid];
        else                     s_et[tid - EE] = et_g[tid - EE];
        if (tid == 0) { sh_qmax = -INFINITY; sh_flag = 0; }

        // initial per-node argmax over RAW node_vals
        int a = tid & 15;
        float bv = v; int bi = a;
        #pragma unroll
        for (int m = 1; m < 16; m <<= 1) {
            float ov = __shfl_xor_sync(full, bv, m, 16);
            int   oi = __shfl_xor_sync(full, bi, m, 16);
            if (ov > bv || (ov == bv && oi < bi)) { bv = ov; bi = oi; }
        }
        if (a == 0) s_a[tid >> 4] = bi;
    }
    __syncthreads();

    // ---------------- CSR adjacency build (deterministic, ascending e) ------
    {
        if (tid < NN) {
            int c = 0;
            for (int e = 0; e < EE; e++) if (s_et[e] == tid) c++;
            s_ino[tid + 1] = c;
        } else if (tid < 2 * NN) {
            int n = tid - NN; int c = 0;
            for (int e = 0; e < EE; e++) if (s_ef[e] == n) c++;
            s_out[n + 1] = c;
        }
        __syncthreads();
        if (tid == 0) {
            s_ino[0] = 0; s_out[0] = 0;
            for (int n = 0; n < NN; n++) {
                s_ino[n + 1] += s_ino[n];
                s_out[n + 1] += s_out[n];
            }
        }
        __syncthreads();
        if (tid < NN) {
            int c = s_ino[tid];
            for (int e = 0; e < EE; e++) if (s_et[e] == tid) s_inl[c++] = e;
        } else if (tid < 2 * NN) {
            int n = tid - NN; int c = s_out[n];
            for (int e = 0; e < EE; e++) if (s_ef[e] == n) s_onl[c++] = e;
        }
    }
    __syncthreads();

    // ---------------- eval helper ----------------
    auto do_eval = [&]() {
        float contrib = 0.f;
        if (tid < NN)
            contrib += s_nv[tid * AA + s_a[tid]] * (1.0f / NN);
        if (tid < EE) {
            int e  = tid;
            int af = s_a[s_ef[e]];
            int at = s_a[s_et[e]];
            contrib += __ldg(&edge_vals[(((size_t)b * EE + e) * AA + af) * AA + at])
                       * (1.0f / EE);
        }
        #pragma unroll
        for (int m = 16; m > 0; m >>= 1)
            contrib += __shfl_xor_sync(full, contrib, m);
        if (lane == 0) s_red[warp] = contrib;
        __syncthreads();
        if (warp == 0) {
            float v = s_red[lane];
            #pragma unroll
            for (int m = 16; m > 0; m >>= 1)
                v += __shfl_xor_sync(full, v, m);
            if (lane == 0) {
                if (v > sh_qmax) { sh_qmax = v; sh_flag = 1; }
                else             { sh_flag = 0; }
            }
        }
        __syncthreads();
        if (sh_flag && tid < NN) s_am[tid] = s_a[tid];
        __syncthreads();
    };

    do_eval();   // iteration-0 eval of raw argmax assignment

    const int tsel = lane >> 4;      // which of the warp's 2 concurrent tiles
    const int tl   = lane & 15;      // lane within tile
    const int rg   = tl >> 2;        // row group: rows 4*rg .. 4*rg+3
    const int kg   = tl & 3;         // col group: cols 4*kg .. 4*kg+3

    // ---------------- 8 message-passing iterations ----------------
    for (int it = 0; it < ITERS; it++) {
        // ---- message phase: 32 warps x 8 tile-pairs; 4x4 blocks per lane ----
        {
            const float sc = 1.0f / EE;
            #pragma unroll 2
            for (int i = 0; i < 8; i++) {
                int e = (warp << 4) + (i << 1) + tsel;
                const float4* tile4 =
                    (const float4*)(edge_vals + (((size_t)b * EE + e) << 8));
                int nf = s_ef[e], nt = s_et[e];
                float* mfp = s_mf + (e << 4);
                float* mbp = s_mb + (e << 4);

                // d[at] = q[to][at] - mf_old[at]   (this lane's 4 cols, group kg)
                float4 qt4  = ((const float4*)(s_q + (nt << 4)))[kg];
                float4 mfo4 = ((const float4*)mfp)[kg];
                float4 d4 = make_float4(qt4.x - mfo4.x, qt4.y - mfo4.y,
                                        qt4.z - mfo4.z, qt4.w - mfo4.w);
                // c[af] = q[from][af] - mb_old[af] (this lane's 4 rows, group rg)
                float4 qf4  = ((const float4*)(s_q + (nf << 4)))[rg];
                float4 mbo4 = ((const float4*)mbp)[rg];
                float4 c4 = make_float4(qf4.x - mbo4.x, qf4.y - mbo4.y,
                                        qf4.z - mbo4.z, qf4.w - mbo4.w);

                float4 f4, m4, v;
                int base = (rg << 4) + kg;      // float4 index of (row 4rg, colgrp kg)

                // j = 0 : row 4rg+0
                v = __ldg(tile4 + base);
                v.x *= sc; v.y *= sc; v.z *= sc; v.w *= sc;
                m4.x = fmaxf(fmaxf(d4.x + v.x, d4.y + v.y),
                             fmaxf(d4.z + v.z, d4.w + v.w));
                f4.x = c4.x + v.x; f4.y = c4.x + v.y;
                f4.z = c4.x + v.z; f4.w = c4.x + v.w;
                // j = 1 : row 4rg+1
                v = __ldg(tile4 + base + 4);
                v.x *= sc; v.y *= sc; v.z *= sc; v.w *= sc;
                m4.y = fmaxf(fmaxf(d4.x + v.x, d4.y + v.y),
                             fmaxf(d4.z + v.z, d4.w + v.w));
                f4.x = fmaxf(f4.x, c4.y + v.x); f4.y = fmaxf(f4.y, c4.y + v.y);
                f4.z = fmaxf(f4.z, c4.y + v.z); f4.w = fmaxf(f4.w, c4.y + v.w);
                // j = 2 : row 4rg+2
                v = __ldg(tile4 + base + 8);
                v.x *= sc; v.y *= sc; v.z *= sc; v.w *= sc;
                m4.z = fmaxf(fmaxf(d4.x + v.x, d4.y + v.y),
                             fmaxf(d4.z + v.z, d4.w + v.w));
                f4.x = fmaxf(f4.x, c4.z + v.x); f4.y = fmaxf(f4.y, c4.z + v.y);
                f4.z = fmaxf(f4.z, c4.z + v.z); f4.w = fmaxf(f4.w, c4.z + v.w);
                // j = 3 : row 4rg+3
                v = __ldg(tile4 + base + 12);
                v.x *= sc; v.y *= sc; v.z *= sc; v.w *= sc;
                m4.w = fmaxf(fmaxf(d4.x + v.x, d4.y + v.y),
                             fmaxf(d4.z + v.z, d4.w + v.w));
                f4.x = fmaxf(f4.x, c4.w + v.x); f4.y = fmaxf(f4.y, c4.w + v.y);
                f4.z = fmaxf(f4.z, c4.w + v.z); f4.w = fmaxf(f4.w, c4.w + v.w);

                // reduce row-maxes (mb) over the 4 col-groups: xor 1, 2 (exact max)
                m4.x = fmaxf(m4.x, __shfl_xor_sync(full, m4.x, 1));
                m4.y = fmaxf(m4.y, __shfl_xor_sync(full, m4.y, 1));
                m4.z = fmaxf(m4.z, __shfl_xor_sync(full, m4.z, 1));
                m4.w = fmaxf(m4.w, __shfl_xor_sync(full, m4.w, 1));
                m4.x = fmaxf(m4.x, __shfl_xor_sync(full, m4.x, 2));
                m4.y = fmaxf(m4.y, __shfl_xor_sync(full, m4.y, 2));
                m4.z = fmaxf(m4.z, __shfl_xor_sync(full, m4.z, 2));
                m4.w = fmaxf(m4.w, __shfl_xor_sync(full, m4.w, 2));

                // reduce col-maxes (mf) over the 4 row-groups: xor 4, 8 (exact max)
                f4.x = fmaxf(f4.x, __shfl_xor_sync(full, f4.x, 4));
                f4.y = fmaxf(f4.y, __shfl_xor_sync(full, f4.y, 4));
                f4.z = fmaxf(f4.z, __shfl_xor_sync(full, f4.z, 4));
                f4.w = fmaxf(f4.w, __shfl_xor_sync(full, f4.w, 4));
                f4.x = fmaxf(f4.x, __shfl_xor_sync(full, f4.x, 8));
                f4.y = fmaxf(f4.y, __shfl_xor_sync(full, f4.y, 8));
                f4.z = fmaxf(f4.z, __shfl_xor_sync(full, f4.z, 8));
                f4.w = fmaxf(f4.w, __shfl_xor_sync(full, f4.w, 8));

                // mean-center mf over 16 'at' (serial 4 + xor1 + xor2)
                float s = f4.x + f4.y + f4.z + f4.w;
                s += __shfl_xor_sync(full, s, 1);
                s += __shfl_xor_sync(full, s, 2);
                s *= (1.0f / AA);
                f4.x -= s; f4.y -= s; f4.z -= s; f4.w -= s;

                // mean-center mb over 16 'af' — exact R6/R8 sum tree
                float4 t4;
                t4.x = m4.x + __shfl_xor_sync(full, m4.x, 8);
                t4.y = m4.y + __shfl_xor_sync(full, m4.y, 8);
                t4.z = m4.z + __shfl_xor_sync(full, m4.z, 8);
                t4.w = m4.w + __shfl_xor_sync(full, m4.w, 8);
                float sm = (t4.x + t4.y) + (t4.z + t4.w);
                sm += __shfl_xor_sync(full, sm, 4);
                sm *= (1.0f / AA);
                m4.x -= sm; m4.y -= sm; m4.z -= sm; m4.w -= sm;

                if (rg == 0) ((float4*)mfp)[kg] = f4;
                if (kg == 0) ((float4*)mbp)[rg] = m4;
            }
        }
        __syncthreads();

        // ---- node update + argmax (single pass: 1024 threads == NN*AA) ----
        {
            int n = tid >> 4, a = tid & 15;
            float v = s_nv[tid] * (1.0f / NN);
            int i0 = s_ino[n], i1 = s_ino[n + 1];
            for (int i = i0; i < i1; i++) v += s_mf[(s_inl[i] << 4) + a];
            int o0 = s_out[n], o1 = s_out[n + 1];
            for (int i = o0; i < o1; i++) v += s_mb[(s_onl[i] << 4) + a];
            s_q[tid] = v;

            float bv = v; int bi = a;
            #pragma unroll
            for (int m = 1; m < 16; m <<= 1) {
                float ov = __shfl_xor_sync(full, bv, m, 16);
                int   oi = __shfl_xor_sync(full, bi, m, 16);
                if (ov > bv || (ov == bv && oi < bi)) { bv = ov; bi = oi; }
            }
            if (a == 0) s_a[n] = bi;
        }
        __syncthreads();

        // ---- eval current assignment, keep best ----
        do_eval();
    }

    // ---------------- write results directly ----------------
    int tot = BB + BB * NN;
    if (out_size >= tot) {
        if (tid == 0) out[b] = sh_qmax;
        if (tid < NN) out[BB + b * NN + tid] = (float)s_am[tid];
    } else if (out_size == BB * NN) {
        if (tid < NN) out[b * NN + tid] = (float)s_am[tid];
    } else {
        if (tid == 0 && b < out_size) out[b] = sh_qmax;
    }
}

// ---------------- launch ----------------------------------------------------
extern "C" void kernel_launch(void* const* d_in, const int* in_sizes, int n_in,
                              void* d_out, int out_size) {
    const float* node_vals = (const float*)d_in[0];
    const float* edge_vals = (const float*)d_in[1];
    const int*   ef        = (const int*)d_in[2];
    const int*   et        = (const int*)d_in[3];
    float* out = (float*)d_out;

    cudaFuncSetAttribute(k_main, cudaFuncAttributeMaxDynamicSharedMemorySize,
                         SMEM_BYTES);

    k_main<<<BB, THREADS, SMEM_BYTES>>>(node_vals, edge_vals, ef, et,
                                        out, out_size);
}